// round 2
// baseline (speedup 1.0000x reference)
#include <cuda_runtime.h>
#include <cuda_bf16.h>

#define BATCH 8
#define NPTS  32768
#define NCH   96
#define NSAMP 1024
#define THREADS 1024
#define NPT (NPTS / THREADS)   // 32 points per thread

// Scratch: selected indices per batch (no device allocation allowed).
__device__ int g_idx[BATCH * NSAMP];

// ---------------------------------------------------------------------------
// FPS kernel: one CTA per batch, 1024 threads, running min-dists in registers.
// Emits: out_xyz (B,S,3), out_idxf (B,S) as float, g_idx (int) for gather.
// ---------------------------------------------------------------------------
__global__ __launch_bounds__(THREADS, 1)
void fps_kernel(const float* __restrict__ xyz,
                float* __restrict__ out_xyz,
                float* __restrict__ out_idxf)
{
    const int b = blockIdx.x;
    const float* __restrict__ p = xyz + (size_t)b * NPTS * 3;

    float dist[NPT];
#pragma unroll
    for (int i = 0; i < NPT; i++) dist[i] = 1e10f;

    __shared__ float sdist[32];
    __shared__ int   sidx[32];
    __shared__ int   s_cur;

    const int tid  = threadIdx.x;
    const int lane = tid & 31;
    const int warp = tid >> 5;

    int cur = 0;

    for (int s = 0; s < NSAMP; s++) {
        // Broadcast current point coords (same address, L1 broadcast).
        const float cx = __ldg(p + 3 * cur + 0);
        const float cy = __ldg(p + 3 * cur + 1);
        const float cz = __ldg(p + 3 * cur + 2);

        if (tid == 0) {
            g_idx[b * NSAMP + s]    = cur;
            out_idxf[b * NSAMP + s] = (float)cur;
            float* o = out_xyz + ((size_t)b * NSAMP + s) * 3;
            o[0] = cx; o[1] = cy; o[2] = cz;
        }

        float bd = -1.0f;
        int   bi = 0;
#pragma unroll
        for (int i = 0; i < NPT; i++) {
            const int j = tid + i * THREADS;           // ascending within thread
            const float dx = __fadd_rn(p[3 * j + 0], -cx);
            const float dy = __fadd_rn(p[3 * j + 1], -cy);
            const float dz = __fadd_rn(p[3 * j + 2], -cz);
            // (dx*dx + dy*dy) + dz*dz, no FMA contraction (match XLA fp32 order)
            const float d = __fadd_rn(__fadd_rn(__fmul_rn(dx, dx),
                                                __fmul_rn(dy, dy)),
                                      __fmul_rn(dz, dz));
            const float nd = fminf(dist[i], d);
            dist[i] = nd;
            if (nd > bd) { bd = nd; bi = j; }          // strict > keeps smallest j
        }

        // Warp reduction: larger dist wins; tie -> smaller index.
#pragma unroll
        for (int off = 16; off > 0; off >>= 1) {
            const float od = __shfl_down_sync(0xffffffffu, bd, off);
            const int   oi = __shfl_down_sync(0xffffffffu, bi, off);
            if (od > bd || (od == bd && oi < bi)) { bd = od; bi = oi; }
        }
        if (lane == 0) { sdist[warp] = bd; sidx[warp] = bi; }
        __syncthreads();

        if (warp == 0) {
            float wbd = sdist[lane];
            int   wbi = sidx[lane];
#pragma unroll
            for (int off = 16; off > 0; off >>= 1) {
                const float od = __shfl_down_sync(0xffffffffu, wbd, off);
                const int   oi = __shfl_down_sync(0xffffffffu, wbi, off);
                if (od > wbd || (od == wbd && oi < wbi)) { wbd = od; wbi = oi; }
            }
            if (lane == 0) s_cur = wbi;
        }
        __syncthreads();
        cur = s_cur;
    }
}

// ---------------------------------------------------------------------------
// Feature gather: out_fea[b][c][s] = fea[b][c][g_idx[b][s]]
// ---------------------------------------------------------------------------
__global__ void gather_kernel(const float* __restrict__ fea,
                              float* __restrict__ out_fea)
{
    const int t = blockIdx.x * blockDim.x + threadIdx.x;
    if (t >= BATCH * NCH * NSAMP) return;
    const int s = t % NSAMP;
    const int c = (t / NSAMP) % NCH;
    const int b = t / (NCH * NSAMP);
    const int id = g_idx[b * NSAMP + s];
    out_fea[t] = __ldg(fea + ((size_t)b * NCH + c) * NPTS + id);
}

extern "C" void kernel_launch(void* const* d_in, const int* in_sizes, int n_in,
                              void* d_out, int out_size)
{
    const float* xyz = (const float*)d_in[0];   // (B, N, 3)
    const float* fea = (const float*)d_in[1];   // (B, C, N)

    float* out = (float*)d_out;
    // Output layout: new_xyz (B,S,3) | new_fea (B,C,S) | indices-as-float (B,S)
    float* out_xyz  = out;
    float* out_fea  = out + (size_t)BATCH * NSAMP * 3;
    float* out_idxf = out + (size_t)BATCH * NSAMP * 3 + (size_t)BATCH * NCH * NSAMP;

    fps_kernel<<<BATCH, THREADS>>>(xyz, out_xyz, out_idxf);

    const int total = BATCH * NCH * NSAMP;
    gather_kernel<<<(total + 255) / 256, 256>>>(fea, out_fea);
}

// round 5
// speedup vs baseline: 1.6260x; 1.6260x over previous
#include <cuda_runtime.h>
#include <cuda_bf16.h>

#define BATCH 8
#define NPTS  32768
#define NCH   96
#define NSAMP 1024
#define CSZ   8                 // cluster size (CTAs per batch)
#define NL    (NPTS / CSZ)      // 4096 points per CTA
#define T     1024
#define PPT   (NL / T)          // 4 points per thread

// Scratch (no device allocation allowed): selected indices + cross-CTA mailbox.
__device__ int    g_idx[BATCH * NSAMP];
__device__ float4 g_mb [2][BATCH][CSZ];   // {best_dist, x, y, z} per CTA
__device__ int    g_mbi[2][BATCH][CSZ];   // best global index per CTA

__device__ __forceinline__ void red_pair(float od, int oi, float& bd, int& bi) {
    // larger dist wins; tie -> smaller global index (matches jnp.argmax first-occurrence)
    if (od > bd || (od == bd && oi < bi)) { bd = od; bi = oi; }
}

// ---------------------------------------------------------------------------
// FPS: 8-CTA cluster per batch. Each CTA holds its 4096-point slice SoA in
// smem; per-iteration global argmax via mailbox + cluster barrier.
// ---------------------------------------------------------------------------
__global__ void __cluster_dims__(CSZ, 1, 1) __launch_bounds__(T, 1)
fps_kernel(const float* __restrict__ xyz,
           float* __restrict__ out_xyz,
           float* __restrict__ out_idxf)
{
    extern __shared__ float smem[];
    float* sx  = smem;
    float* sy  = smem + NL;
    float* sz  = smem + 2 * NL;
    float* swd = smem + 3 * NL;          // 32 floats
    int*   swi = (int*)(smem + 3 * NL + 32);  // 32 ints

    const int rank = blockIdx.x;         // cluster rank (0..7)
    const int b    = blockIdx.y;         // batch
    const int tid  = threadIdx.x;
    const int lane = tid & 31;
    const int warp = tid >> 5;
    const int base = rank * NL;
    const float* __restrict__ p = xyz + (size_t)b * NPTS * 3;

    // One-time: load this CTA's AoS slice -> SoA smem (coalesced global reads).
    for (int f = tid; f < NL * 3; f += T) {
        const float v = p[base * 3 + f];
        const int i = f / 3, c = f - 3 * i;
        float* d = (c == 0) ? sx : ((c == 1) ? sy : sz);
        d[i] = v;
    }
    __syncthreads();

    float dist[PPT];
#pragma unroll
    for (int i = 0; i < PPT; i++) dist[i] = 1e10f;

    // First centroid is global index 0 (reference convention).
    float cx = __ldg(p + 0), cy = __ldg(p + 1), cz = __ldg(p + 2);
    int cur = 0;

    const float4* sx4 = (const float4*)sx;
    const float4* sy4 = (const float4*)sy;
    const float4* sz4 = (const float4*)sz;

    for (int s = 0; s < NSAMP; s++) {
        if (rank == 0 && tid == 0) {
            g_idx[b * NSAMP + s]    = cur;
            out_idxf[b * NSAMP + s] = (float)cur;
            float* o = out_xyz + ((size_t)b * NSAMP + s) * 3;
            o[0] = cx; o[1] = cy; o[2] = cz;
        }

        // Vectorized SoA scan: 4 points per thread from smem.
        const float4 x4 = sx4[tid], y4 = sy4[tid], z4 = sz4[tid];
        const float xs[4] = {x4.x, x4.y, x4.z, x4.w};
        const float ys[4] = {y4.x, y4.y, y4.z, y4.w};
        const float zs[4] = {z4.x, z4.y, z4.z, z4.w};

        float bd = -1.0f; int bi = 0;
#pragma unroll
        for (int i = 0; i < PPT; i++) {
            const float dx = __fadd_rn(xs[i], -cx);
            const float dy = __fadd_rn(ys[i], -cy);
            const float dz = __fadd_rn(zs[i], -cz);
            // (dx*dx + dy*dy) + dz*dz with no FMA contraction (bit-match XLA)
            const float d = __fadd_rn(__fadd_rn(__fmul_rn(dx, dx),
                                                __fmul_rn(dy, dy)),
                                      __fmul_rn(dz, dz));
            const float nd = fminf(dist[i], d);
            dist[i] = nd;
            if (nd > bd) { bd = nd; bi = tid * PPT + i; }  // ascending j: strict >
        }
        bi += base;  // globalize

        // Intra-warp reduce.
#pragma unroll
        for (int off = 16; off > 0; off >>= 1) {
            const float od = __shfl_down_sync(0xffffffffu, bd, off);
            const int   oi = __shfl_down_sync(0xffffffffu, bi, off);
            red_pair(od, oi, bd, bi);
        }
        if (lane == 0) { swd[warp] = bd; swi[warp] = bi; }
        __syncthreads();

        // Cross-warp reduce in warp 0, then publish to mailbox (with coords).
        if (warp == 0) {
            bd = swd[lane]; bi = swi[lane];
#pragma unroll
            for (int off = 16; off > 0; off >>= 1) {
                const float od = __shfl_down_sync(0xffffffffu, bd, off);
                const int   oi = __shfl_down_sync(0xffffffffu, bi, off);
                red_pair(od, oi, bd, bi);
            }
            if (lane == 0) {
                const int lj = bi - base;
                g_mb [s & 1][b][rank] = make_float4(bd, sx[lj], sy[lj], sz[lj]);
                g_mbi[s & 1][b][rank] = bi;
                __threadfence();
            }
        }

        // Cluster barrier: all 8 CTAs' mailbox entries visible afterwards.
        asm volatile("barrier.cluster.arrive.aligned;\n" ::: "memory");
        asm volatile("barrier.cluster.wait.aligned;\n"   ::: "memory");

        // Every warp reads the 8 mailbox entries (L2, bypass L1) and reduces.
        float md = -1.0f, mx = 0.f, my = 0.f, mz = 0.f; int mi = 0;
        if (lane < CSZ) {
            const float4 m = __ldcg(&g_mb[s & 1][b][lane]);
            mi = __ldcg(&g_mbi[s & 1][b][lane]);
            md = m.x; mx = m.y; my = m.z; mz = m.w;
        }
#pragma unroll
        for (int off = 4; off > 0; off >>= 1) {
            const float od = __shfl_xor_sync(0xffffffffu, md, off);
            const int   oi = __shfl_xor_sync(0xffffffffu, mi, off);
            const float ox = __shfl_xor_sync(0xffffffffu, mx, off);
            const float oy = __shfl_xor_sync(0xffffffffu, my, off);
            const float oz = __shfl_xor_sync(0xffffffffu, mz, off);
            if (od > md || (od == md && oi < mi)) { md = od; mi = oi; mx = ox; my = oy; mz = oz; }
        }
        cur = __shfl_sync(0xffffffffu, mi, 0);
        cx  = __shfl_sync(0xffffffffu, mx, 0);
        cy  = __shfl_sync(0xffffffffu, my, 0);
        cz  = __shfl_sync(0xffffffffu, mz, 0);
    }
}

// ---------------------------------------------------------------------------
// Feature gather: out_fea[b][c][s] = fea[b][c][g_idx[b][s]]
// ---------------------------------------------------------------------------
__global__ void gather_kernel(const float* __restrict__ fea,
                              float* __restrict__ out_fea)
{
    const int t = blockIdx.x * blockDim.x + threadIdx.x;
    if (t >= BATCH * NCH * NSAMP) return;
    const int s = t % NSAMP;
    const int c = (t / NSAMP) % NCH;
    const int b = t / (NCH * NSAMP);
    const int id = g_idx[b * NSAMP + s];
    out_fea[t] = __ldg(fea + ((size_t)b * NCH + c) * NPTS + id);
}

extern "C" void kernel_launch(void* const* d_in, const int* in_sizes, int n_in,
                              void* d_out, int out_size)
{
    const float* xyz = (const float*)d_in[0];   // (B, N, 3)
    const float* fea = (const float*)d_in[1];   // (B, C, N)

    float* out = (float*)d_out;
    // Output layout: new_xyz (B,S,3) | new_fea (B,C,S) | indices-as-float (B,S)
    float* out_xyz  = out;
    float* out_fea  = out + (size_t)BATCH * NSAMP * 3;
    float* out_idxf = out + (size_t)BATCH * NSAMP * 3 + (size_t)BATCH * NCH * NSAMP;

    const int smem_bytes = (3 * NL + 64) * (int)sizeof(float);  // SoA + reduce buffers
    static_assert((3 * NL + 64) * sizeof(float) <= 64 * 1024, "smem");
    cudaFuncSetAttribute(fps_kernel, cudaFuncAttributeMaxDynamicSharedMemorySize, smem_bytes);

    fps_kernel<<<dim3(CSZ, BATCH), T, smem_bytes>>>(xyz, out_xyz, out_idxf);

    const int total = BATCH * NCH * NSAMP;
    gather_kernel<<<(total + 255) / 256, 256>>>(fea, out_fea);
}

// round 7
// speedup vs baseline: 3.0245x; 1.8601x over previous
#include <cuda_runtime.h>
#include <cuda_bf16.h>

#define BATCH 8
#define NPTS  32768
#define NCH   96
#define NSAMP 1024
#define CSZ   8                 // CTAs per batch (cluster)
#define NL    (NPTS / CSZ)      // 4096 points per CTA
#define T     512
#define PPT   (NL / T)          // 8 points per thread
#define NPAIR (PPT / 2)         // 4 packed pairs
#define NWARP (T / 32)          // 16 warps

// Scratch (no device allocation allowed).
__device__ int g_idx[BATCH * NSAMP];

// ---------------- packed f32x2 helpers (per-lane IEEE rn => bit-exact) -----
typedef unsigned long long ull;
__device__ __forceinline__ ull pk(float a, float b) {
    ull r; asm("mov.b64 %0, {%1,%2};" : "=l"(r) : "f"(a), "f"(b)); return r;
}
__device__ __forceinline__ void upk(ull v, float& a, float& b) {
    asm("mov.b64 {%0,%1}, %2;" : "=f"(a), "=f"(b) : "l"(v));
}
__device__ __forceinline__ ull addx2(ull a, ull b) {
    ull r; asm("add.rn.f32x2 %0, %1, %2;" : "=l"(r) : "l"(a), "l"(b)); return r;
}
__device__ __forceinline__ ull mulx2(ull a, ull b) {
    ull r; asm("mul.rn.f32x2 %0, %1, %2;" : "=l"(r) : "l"(a), "l"(b)); return r;
}
__device__ __forceinline__ unsigned su32(const void* p) {
    unsigned r;
    asm("{.reg .u64 t; cvta.to.shared.u64 t, %1; cvt.u32.u64 %0, t;}" : "=r"(r) : "l"(p));
    return r;
}
__device__ __forceinline__ void red_pair(float od, int oi, float& bd, int& bi) {
    // larger dist wins; tie -> smaller global index (jnp.argmax first-occurrence)
    if (od > bd || (od == bd && oi < bi)) { bd = od; bi = oi; }
}

// ---------------------------------------------------------------------------
// FPS: 8-CTA cluster per batch. Coords in registers; DSMEM push mailbox with
// release/acquire tags (no cluster barrier, no threadfence, no L2 round-trip).
// ---------------------------------------------------------------------------
__global__ void __cluster_dims__(CSZ, 1, 1) __launch_bounds__(T, 1)
fps_kernel(const float* __restrict__ xyz,
           float* __restrict__ out_xyz,
           float* __restrict__ out_idxf)
{
    extern __shared__ float smem[];
    float*    sx  = smem;                       // winner-coord lookup copies
    float*    sy  = smem + NL;
    float*    sz  = smem + 2 * NL;
    unsigned* mb  = (unsigned*)(smem + 3 * NL); // mailbox [2][CSZ][6]: d,x,y,z,idx,tag
    float*    swd = (float*)(mb + 2 * CSZ * 6);
    int*      swi = (int*)(swd + NWARP);

    const int rank = blockIdx.x;
    const int b    = blockIdx.y;
    const int tid  = threadIdx.x;
    const int lane = tid & 31;
    const int warp = tid >> 5;
    const int base = rank * NL;
    const float* __restrict__ p = xyz + (size_t)b * NPTS * 3;

    // ---- one-time: load my 8 points into registers + smem lookup copy ----
    float X[PPT], Y[PPT], Z[PPT];
    {
        float buf[24];
        const float4* p4 = (const float4*)(p + (size_t)(base + tid * PPT) * 3);
#pragma unroll
        for (int k = 0; k < 6; k++) ((float4*)buf)[k] = p4[k];
#pragma unroll
        for (int i = 0; i < PPT; i++) {
            X[i] = buf[3 * i]; Y[i] = buf[3 * i + 1]; Z[i] = buf[3 * i + 2];
            sx[tid * PPT + i] = X[i];
            sy[tid * PPT + i] = Y[i];
            sz[tid * PPT + i] = Z[i];
        }
    }
    ull x2[NPAIR], y2[NPAIR], z2[NPAIR];
#pragma unroll
    for (int q = 0; q < NPAIR; q++) {
        x2[q] = pk(X[2 * q], X[2 * q + 1]);
        y2[q] = pk(Y[2 * q], Y[2 * q + 1]);
        z2[q] = pk(Z[2 * q], Z[2 * q + 1]);
    }

    // ---- init mailbox tags, then one cluster barrier before any push ----
    if (tid < 2 * CSZ * 6) mb[tid] = 0xFFFFFFFFu;
    __syncthreads();
    asm volatile("barrier.cluster.arrive.aligned;\n" ::: "memory");
    asm volatile("barrier.cluster.wait.aligned;\n"   ::: "memory");

    // Precompute remote slot addresses (warp0 lanes 0..7 push to peer==lane).
    const unsigned mb_u = su32(mb);
    unsigned rem0 = 0, rem1 = 0;
    if (warp == 0 && lane < CSZ) {
        const unsigned l0 = mb_u + (unsigned)((0 * CSZ + rank) * 6) * 4u;
        const unsigned l1 = mb_u + (unsigned)((1 * CSZ + rank) * 6) * 4u;
        asm("mapa.shared::cluster.u32 %0, %1, %2;" : "=r"(rem0) : "r"(l0), "r"(lane));
        asm("mapa.shared::cluster.u32 %0, %1, %2;" : "=r"(rem1) : "r"(l1), "r"(lane));
    }

    float dist[PPT];
#pragma unroll
    for (int i = 0; i < PPT; i++) dist[i] = 1e10f;

    int   cur = 0;
    float cx = __ldg(p + 0), cy = __ldg(p + 1), cz = __ldg(p + 2);

    for (int s = 0; s < NSAMP; s++) {
        if (rank == 0 && tid == 0) {
            g_idx[b * NSAMP + s]    = cur;
            out_idxf[b * NSAMP + s] = (float)cur;
            float* o = out_xyz + ((size_t)b * NSAMP + s) * 3;
            o[0] = cx; o[1] = cy; o[2] = cz;
        }

        // ---- scan: packed (x-c)^2 ordering (dx*dx+dy*dy)+dz*dz, rn ----
        const ull ncx2 = pk(-cx, -cx), ncy2 = pk(-cy, -cy), ncz2 = pk(-cz, -cz);
#pragma unroll
        for (int q = 0; q < NPAIR; q++) {
            const ull dx2 = addx2(x2[q], ncx2);
            const ull dy2 = addx2(y2[q], ncy2);
            const ull dz2 = addx2(z2[q], ncz2);
            const ull d2  = addx2(addx2(mulx2(dx2, dx2), mulx2(dy2, dy2)),
                                  mulx2(dz2, dz2));
            float d0, d1; upk(d2, d0, d1);
            dist[2 * q]     = fminf(dist[2 * q],     d0);
            dist[2 * q + 1] = fminf(dist[2 * q + 1], d1);
        }
        // tree max over 8 dists
        float m01 = fmaxf(dist[0], dist[1]), m23 = fmaxf(dist[2], dist[3]);
        float m45 = fmaxf(dist[4], dist[5]), m67 = fmaxf(dist[6], dist[7]);
        float bd  = fmaxf(fmaxf(m01, m23), fmaxf(m45, m67));
        // first (smallest) local index achieving bd
        int li = 0;
#pragma unroll
        for (int i = PPT - 1; i >= 0; i--) if (dist[i] == bd) li = i;
        int bi = base + tid * PPT + li;

        // ---- intra-warp reduce ----
#pragma unroll
        for (int off = 16; off > 0; off >>= 1) {
            const float od = __shfl_down_sync(0xffffffffu, bd, off);
            const int   oi = __shfl_down_sync(0xffffffffu, bi, off);
            red_pair(od, oi, bd, bi);
        }
        if (lane == 0) { swd[warp] = bd; swi[warp] = bi; }
        __syncthreads();

        // ---- warp0: CTA reduce + DSMEM push to all 8 peers ----
        if (warp == 0) {
            float rd = (lane < NWARP) ? swd[lane] : -1.0f;
            int   ri = (lane < NWARP) ? swi[lane] : 0x7fffffff;
#pragma unroll
            for (int off = 8; off > 0; off >>= 1) {
                const float od = __shfl_down_sync(0xffffffffu, rd, off);
                const int   oi = __shfl_down_sync(0xffffffffu, ri, off);
                red_pair(od, oi, rd, ri);
            }
            rd = __shfl_sync(0xffffffffu, rd, 0);
            ri = __shfl_sync(0xffffffffu, ri, 0);
            if (lane < CSZ) {
                const int lj = ri - base;               // broadcast LDS (same addr)
                const unsigned wd = __float_as_uint(rd);
                const unsigned wx = __float_as_uint(sx[lj]);
                const unsigned wy = __float_as_uint(sy[lj]);
                const unsigned wz = __float_as_uint(sz[lj]);
                const unsigned rem = (s & 1) ? rem1 : rem0;
                asm volatile("st.shared::cluster.u32 [%0], %1;" :: "r"(rem +  0u), "r"(wd));
                asm volatile("st.shared::cluster.u32 [%0], %1;" :: "r"(rem +  4u), "r"(wx));
                asm volatile("st.shared::cluster.u32 [%0], %1;" :: "r"(rem +  8u), "r"(wy));
                asm volatile("st.shared::cluster.u32 [%0], %1;" :: "r"(rem + 12u), "r"(wz));
                asm volatile("st.shared::cluster.u32 [%0], %1;" :: "r"(rem + 16u), "r"((unsigned)ri));
                asm volatile("st.release.cluster.shared::cluster.u32 [%0], %1;"
                             :: "r"(rem + 20u), "r"((unsigned)s));
            }
        }

        // ---- every warp: spin on local tags, then reduce 8 candidates ----
        const unsigned tag_a = mb_u + (unsigned)((((s & 1) * CSZ + lane) * 6 + 5)) * 4u;
        int ok;
        do {
            unsigned t = (unsigned)s;
            if (lane < CSZ)
                asm volatile("ld.acquire.cluster.shared::cta.u32 %0, [%1];"
                             : "=r"(t) : "r"(tag_a));
            ok = __all_sync(0xffffffffu, t == (unsigned)s);
        } while (!ok);

        float md = -1.0f, mx = 0.f, my = 0.f, mz = 0.f; int mi = 0x7fffffff;
        if (lane < CSZ) {
            const unsigned* slot = mb + ((s & 1) * CSZ + lane) * 6;
            md = __uint_as_float(slot[0]);
            mx = __uint_as_float(slot[1]);
            my = __uint_as_float(slot[2]);
            mz = __uint_as_float(slot[3]);
            mi = (int)slot[4];
        }
#pragma unroll
        for (int off = 4; off > 0; off >>= 1) {
            const float od = __shfl_xor_sync(0xffffffffu, md, off);
            const int   oi = __shfl_xor_sync(0xffffffffu, mi, off);
            const float ox = __shfl_xor_sync(0xffffffffu, mx, off);
            const float oy = __shfl_xor_sync(0xffffffffu, my, off);
            const float oz = __shfl_xor_sync(0xffffffffu, mz, off);
            if (od > md || (od == md && oi < mi)) { md = od; mi = oi; mx = ox; my = oy; mz = oz; }
        }
        cur = __shfl_sync(0xffffffffu, mi, 0);
        cx  = __shfl_sync(0xffffffffu, mx, 0);
        cy  = __shfl_sync(0xffffffffu, my, 0);
        cz  = __shfl_sync(0xffffffffu, mz, 0);
    }
}

// ---------------------------------------------------------------------------
// Feature gather: out_fea[b][c][s] = fea[b][c][g_idx[b][s]]
// ---------------------------------------------------------------------------
__global__ void gather_kernel(const float* __restrict__ fea,
                              float* __restrict__ out_fea)
{
    const int t = blockIdx.x * blockDim.x + threadIdx.x;
    if (t >= BATCH * NCH * NSAMP) return;
    const int s = t % NSAMP;
    const int c = (t / NSAMP) % NCH;
    const int b = t / (NCH * NSAMP);
    const int id = g_idx[b * NSAMP + s];
    out_fea[t] = __ldg(fea + ((size_t)b * NCH + c) * NPTS + id);
}

extern "C" void kernel_launch(void* const* d_in, const int* in_sizes, int n_in,
                              void* d_out, int out_size)
{
    const float* xyz = (const float*)d_in[0];   // (B, N, 3)
    const float* fea = (const float*)d_in[1];   // (B, C, N)

    float* out = (float*)d_out;
    // Output layout: new_xyz (B,S,3) | new_fea (B,C,S) | indices-as-float (B,S)
    float* out_xyz  = out;
    float* out_fea  = out + (size_t)BATCH * NSAMP * 3;
    float* out_idxf = out + (size_t)BATCH * NSAMP * 3 + (size_t)BATCH * NCH * NSAMP;

    const int smem_bytes = 3 * NL * 4            // coord lookup copies
                         + 2 * CSZ * 6 * 4       // mailbox
                         + NWARP * 4 * 2;        // reduce scratch
    cudaFuncSetAttribute(fps_kernel, cudaFuncAttributeMaxDynamicSharedMemorySize, smem_bytes);

    fps_kernel<<<dim3(CSZ, BATCH), T, smem_bytes>>>(xyz, out_xyz, out_idxf);

    const int total = BATCH * NCH * NSAMP;
    gather_kernel<<<(total + 255) / 256, 256>>>(fea, out_fea);
}

// round 8
// speedup vs baseline: 4.2146x; 1.3935x over previous
#include <cuda_runtime.h>
#include <cuda_bf16.h>

#define BATCH 8
#define NPTS  32768
#define NCH   96
#define NSAMP 1024
#define CSZ   8                 // CTAs per batch (cluster)
#define NL    (NPTS / CSZ)      // 4096 points per CTA  (idx>>12 == rank)
#define T     512
#define PPT   (NL / T)          // 8 points per thread
#define NPAIR (PPT / 2)         // 4 packed pairs
#define NWARP (T / 32)          // 16 warps
#define SLOTB 24                // mailbox slot bytes: {d,x | y,z | idx,tag}

// Scratch (no device allocation allowed).
__device__ int g_idx[BATCH * NSAMP];

// ---------------- packed f32x2 helpers (per-lane IEEE rn => bit-exact) -----
typedef unsigned long long ull;
__device__ __forceinline__ ull pk(float a, float b) {
    ull r; asm("mov.b64 %0, {%1,%2};" : "=l"(r) : "f"(a), "f"(b)); return r;
}
__device__ __forceinline__ void upk(ull v, float& a, float& b) {
    asm("mov.b64 {%0,%1}, %2;" : "=f"(a), "=f"(b) : "l"(v));
}
__device__ __forceinline__ ull addx2(ull a, ull b) {
    ull r; asm("add.rn.f32x2 %0, %1, %2;" : "=l"(r) : "l"(a), "l"(b)); return r;
}
__device__ __forceinline__ ull mulx2(ull a, ull b) {
    ull r; asm("mul.rn.f32x2 %0, %1, %2;" : "=l"(r) : "l"(a), "l"(b)); return r;
}
__device__ __forceinline__ unsigned su32(const void* p) {
    unsigned r;
    asm("{.reg .u64 t; cvta.to.shared.u64 t, %1; cvt.u32.u64 %0, t;}" : "=r"(r) : "l"(p));
    return r;
}

// ---------------------------------------------------------------------------
// FPS: 8-CTA cluster per batch. Coords in registers (packed f32x2 scan);
// all argmax levels via redux.sync (dist>=0 => u32-monotonic bits, tiebreak
// = min index via second redux); DSMEM push mailbox, tag fused in release word.
// ---------------------------------------------------------------------------
__global__ void __cluster_dims__(CSZ, 1, 1) __launch_bounds__(T, 1)
fps_kernel(const float* __restrict__ xyz,
           float* __restrict__ out_xyz,
           float* __restrict__ out_idxf)
{
    extern __shared__ float smem[];
    float*    sx   = smem;                        // winner-coord lookup copies
    float*    sy   = smem + NL;
    float*    sz   = smem + 2 * NL;
    unsigned* mb   = (unsigned*)(smem + 3 * NL);  // [2][CSZ] slots of 6 u32
    unsigned* swdb = mb + 2 * CSZ * 6;            // per-warp best dist bits
    unsigned* swi  = swdb + NWARP;                // per-warp best idx

    const int rank = blockIdx.x;
    const int b    = blockIdx.y;
    const int tid  = threadIdx.x;
    const int lane = tid & 31;
    const int warp = tid >> 5;
    const int base = rank * NL;
    const float* __restrict__ p = xyz + (size_t)b * NPTS * 3;

    // ---- one-time: load my 8 points -> packed registers + smem lookup copy
    ull x2[NPAIR], y2[NPAIR], z2[NPAIR];
    {
        float buf[24];
        const float4* p4 = (const float4*)(p + (size_t)(base + tid * PPT) * 3);
#pragma unroll
        for (int k = 0; k < 6; k++) ((float4*)buf)[k] = p4[k];
#pragma unroll
        for (int i = 0; i < PPT; i++) {
            sx[tid * PPT + i] = buf[3 * i];
            sy[tid * PPT + i] = buf[3 * i + 1];
            sz[tid * PPT + i] = buf[3 * i + 2];
        }
#pragma unroll
        for (int q = 0; q < NPAIR; q++) {
            x2[q] = pk(buf[6 * q + 0], buf[6 * q + 3]);
            y2[q] = pk(buf[6 * q + 1], buf[6 * q + 4]);
            z2[q] = pk(buf[6 * q + 2], buf[6 * q + 5]);
        }
    }

    // ---- init mailbox tags (tag = word 5 of each slot) + one cluster barrier
    if (tid < 2 * CSZ) mb[tid * 6 + 5] = 0xFFFFFFFFu;
    __syncthreads();
    asm volatile("barrier.cluster.arrive.aligned;\n" ::: "memory");
    asm volatile("barrier.cluster.wait.aligned;\n"   ::: "memory");

    // Remote slot addresses: warp0 lane r pushes into peer r's slot[parity][rank].
    const unsigned mb_u = su32(mb);
    unsigned rem0 = 0, rem1 = 0;
    if (warp == 0 && lane < CSZ) {
        const unsigned l0 = mb_u + (unsigned)((0 * CSZ + rank) * SLOTB);
        const unsigned l1 = mb_u + (unsigned)((1 * CSZ + rank) * SLOTB);
        asm("mapa.shared::cluster.u32 %0, %1, %2;" : "=r"(rem0) : "r"(l0), "r"(lane));
        asm("mapa.shared::cluster.u32 %0, %1, %2;" : "=r"(rem1) : "r"(l1), "r"(lane));
    }

    float dist[PPT];
#pragma unroll
    for (int i = 0; i < PPT; i++) dist[i] = 1e10f;

    int   cur = 0;
    float cx = __ldg(p + 0), cy = __ldg(p + 1), cz = __ldg(p + 2);

    for (int s = 0; s < NSAMP; s++) {
        if (rank == 0 && tid == 0) {
            g_idx[b * NSAMP + s]    = cur;
            out_idxf[b * NSAMP + s] = (float)cur;
            float* o = out_xyz + ((size_t)b * NSAMP + s) * 3;
            o[0] = cx; o[1] = cy; o[2] = cz;
        }

        // ---- scan: packed (dx*dx+dy*dy)+dz*dz, rn ordering (bit-match XLA)
        const ull ncx2 = pk(-cx, -cx), ncy2 = pk(-cy, -cy), ncz2 = pk(-cz, -cz);
#pragma unroll
        for (int q = 0; q < NPAIR; q++) {
            const ull dx2 = addx2(x2[q], ncx2);
            const ull dy2 = addx2(y2[q], ncy2);
            const ull dz2 = addx2(z2[q], ncz2);
            const ull d2  = addx2(addx2(mulx2(dx2, dx2), mulx2(dy2, dy2)),
                                  mulx2(dz2, dz2));
            float d0, d1; upk(d2, d0, d1);
            dist[2 * q]     = fminf(dist[2 * q],     d0);  // pair (2q, 2q+NPAIR*... )
            dist[2 * q + 1] = fminf(dist[2 * q + 1], d1);
        }
        // packed layout: pair q holds local pts (2? ) -> lanes map: q: pts {q*2? }
        // NOTE: pk() above packed (pt 2q? ) as buf[6q..] => pair q = pts (2q as AoS
        // stride 2): element0 = local pt 2q, element1 = local pt 2q+1.
        // dist[i] corresponds to local pt i with i = 2q (+0/+1)... but packing used
        // buf[6q]/buf[6q+3] = pts (2q) and (2q+1). Consistent.

        // tree max over 8 dists
        const float m01 = fmaxf(dist[0], dist[1]), m23 = fmaxf(dist[2], dist[3]);
        const float m45 = fmaxf(dist[4], dist[5]), m67 = fmaxf(dist[6], dist[7]);
        const float bd  = fmaxf(fmaxf(m01, m23), fmaxf(m45, m67));
        int li = 0;
#pragma unroll
        for (int i = PPT - 1; i >= 0; i--) if (dist[i] == bd) li = i;  // first match
        const unsigned bi = (unsigned)(base + tid * PPT + li);

        // ---- warp reduce via redux (dist>=0 => bits monotone; tie -> min idx)
        const unsigned bdb  = __float_as_uint(bd);
        const unsigned wmax = __reduce_max_sync(0xffffffffu, bdb);
        const unsigned wcnd = (bdb == wmax) ? bi : 0x7fffffffu;
        const unsigned wbi  = __reduce_min_sync(0xffffffffu, wcnd);
        if (lane == 0) { swdb[warp] = wmax; swi[warp] = wbi; }
        __syncthreads();

        // ---- warp0: CTA reduce (redux over 16 warp results) + DSMEM push
        if (warp == 0) {
            const unsigned v = (lane < NWARP) ? swdb[lane] : 0u;
            const unsigned i = (lane < NWARP) ? swi[lane] : 0x7fffffffu;
            const unsigned cmax = __reduce_max_sync(0xffffffffu, v);
            const unsigned ccnd = (v == cmax) ? i : 0x7fffffffu;
            const unsigned ri   = __reduce_min_sync(0xffffffffu, ccnd);
            const int lj = (int)ri - base;                 // uniform -> LDS broadcast
            const unsigned wx = __float_as_uint(sx[lj]);
            const unsigned wy = __float_as_uint(sy[lj]);
            const unsigned wz = __float_as_uint(sz[lj]);
            if (lane < CSZ) {
                const unsigned rem = (s & 1) ? rem1 : rem0;
                asm volatile("st.shared::cluster.v2.b32 [%0], {%1,%2};"
                             :: "r"(rem), "r"(cmax), "r"(wx) : "memory");
                asm volatile("st.shared::cluster.v2.b32 [%0], {%1,%2};"
                             :: "r"(rem + 8u), "r"(wy), "r"(wz) : "memory");
                asm volatile("st.release.cluster.shared::cluster.v2.b32 [%0], {%1,%2};"
                             :: "r"(rem + 16u), "r"(ri), "r"((unsigned)s) : "memory");
            }
        }

        // ---- every warp: spin on fused {idx,tag} words, redux over 8 CTAs
        const unsigned slot_a = mb_u + (unsigned)(((s & 1) * CSZ + lane) * SLOTB);
        unsigned ridx = 0;
        int ok;
        do {
            unsigned tg = (unsigned)s, ti = 0;
            if (lane < CSZ)
                asm volatile("ld.acquire.cluster.shared::cta.v2.b32 {%0,%1}, [%2];"
                             : "=r"(ti), "=r"(tg) : "r"(slot_a + 16u) : "memory");
            ok = __all_sync(0xffffffffu, tg == (unsigned)s);
            ridx = ti;
        } while (!ok);

        unsigned db = 0;
        if (lane < CSZ)
            asm volatile("ld.shared.b32 %0, [%1];" : "=r"(db) : "r"(slot_a) : "memory");
        const unsigned gmax = __reduce_max_sync(0xffffffffu, db);
        const unsigned gcnd = (lane < CSZ && db == gmax) ? ridx : 0x7fffffffu;
        const unsigned wi   = __reduce_min_sync(0xffffffffu, gcnd);
        const unsigned wslot = mb_u + (unsigned)(((s & 1) * CSZ + (wi >> 12)) * SLOTB);
        unsigned bx, by, bz;                                // uniform -> broadcast LDS
        asm volatile("ld.shared.b32 %0, [%1];" : "=r"(bx) : "r"(wslot + 4u) : "memory");
        asm volatile("ld.shared.v2.b32 {%0,%1}, [%2];"
                     : "=r"(by), "=r"(bz) : "r"(wslot + 8u) : "memory");
        cur = (int)wi;
        cx = __uint_as_float(bx); cy = __uint_as_float(by); cz = __uint_as_float(bz);
    }
}

// ---------------------------------------------------------------------------
// Feature gather: out_fea[b][c][s] = fea[b][c][g_idx[b][s]]
// ---------------------------------------------------------------------------
__global__ void gather_kernel(const float* __restrict__ fea,
                              float* __restrict__ out_fea)
{
    const int t = blockIdx.x * blockDim.x + threadIdx.x;
    if (t >= BATCH * NCH * NSAMP) return;
    const int s = t % NSAMP;
    const int c = (t / NSAMP) % NCH;
    const int b = t / (NCH * NSAMP);
    const int id = g_idx[b * NSAMP + s];
    out_fea[t] = __ldg(fea + ((size_t)b * NCH + c) * NPTS + id);
}

extern "C" void kernel_launch(void* const* d_in, const int* in_sizes, int n_in,
                              void* d_out, int out_size)
{
    const float* xyz = (const float*)d_in[0];   // (B, N, 3)
    const float* fea = (const float*)d_in[1];   // (B, C, N)

    float* out = (float*)d_out;
    // Output layout: new_xyz (B,S,3) | new_fea (B,C,S) | indices-as-float (B,S)
    float* out_xyz  = out;
    float* out_fea  = out + (size_t)BATCH * NSAMP * 3;
    float* out_idxf = out + (size_t)BATCH * NSAMP * 3 + (size_t)BATCH * NCH * NSAMP;

    const int smem_bytes = 3 * NL * 4            // coord lookup copies
                         + 2 * CSZ * 6 * 4       // mailbox
                         + NWARP * 4 * 2;        // per-warp reduce scratch
    cudaFuncSetAttribute(fps_kernel, cudaFuncAttributeMaxDynamicSharedMemorySize, smem_bytes);

    fps_kernel<<<dim3(CSZ, BATCH), T, smem_bytes>>>(xyz, out_xyz, out_idxf);

    const int total = BATCH * NCH * NSAMP;
    gather_kernel<<<(total + 255) / 256, 256>>>(fea, out_fea);
}